// round 5
// baseline (speedup 1.0000x reference)
#include <cuda_runtime.h>
#include <cuda_bf16.h>
#include <math.h>
#include <stdint.h>

// ---------------------------------------------------------------------------
// Problem constants
// ---------------------------------------------------------------------------
#define BD      2
#define LSEQ    2048
#define DMODEL  2048
#define NH      16
#define HD      128
#define ROWS    (BD * LSEQ)      // 4096

// ---------------------------------------------------------------------------
// Scratch (device globals -- no allocation allowed)
// ---------------------------------------------------------------------------
__device__ float g_qkv[ROWS * 3 * DMODEL];                 // 96 MB fp32
__device__ float g_x2 [ROWS * DMODEL];                     // 32 MB fp32
__device__ float g_p  [(size_t)ROWS * 8 * DMODEL];         // 256 MB fp32

__device__ __nv_bfloat16 g_xnh[ROWS * DMODEL], g_xnl[ROWS * DMODEL];
__device__ __nv_bfloat16 g_oh [ROWS * DMODEL], g_ol [ROWS * DMODEL];
__device__ __nv_bfloat16 g_ffh[(size_t)ROWS * 4 * DMODEL], g_ffl[(size_t)ROWS * 4 * DMODEL];
// transposed weights [N, K] bf16 hi/lo
__device__ __nv_bfloat16 g_wqkvh[3 * DMODEL * DMODEL], g_wqkvl[3 * DMODEL * DMODEL];
__device__ __nv_bfloat16 g_woh  [DMODEL * DMODEL],     g_wol  [DMODEL * DMODEL];
__device__ __nv_bfloat16 g_wph  [(size_t)8 * DMODEL * DMODEL], g_wpl[(size_t)8 * DMODEL * DMODEL];
__device__ __nv_bfloat16 g_wffh [(size_t)4 * DMODEL * DMODEL], g_wffl[(size_t)4 * DMODEL * DMODEL];

// ---------------------------------------------------------------------------
// Helpers
// ---------------------------------------------------------------------------
__device__ __forceinline__ uint32_t smem_u32(const void* p) {
    uint32_t a;
    asm("{ .reg .u64 t; cvta.to.shared.u64 t, %1; cvt.u32.u64 %0, t; }"
        : "=r"(a) : "l"(p));
    return a;
}
__device__ __forceinline__ void cp16(uint32_t dst, const void* src) {
    asm volatile("cp.async.cg.shared.global [%0], [%1], 16;" :: "r"(dst), "l"(src));
}
__device__ __forceinline__ void ldsm_x4(uint32_t* r, uint32_t a) {
    asm volatile("ldmatrix.sync.aligned.m8n8.x4.shared.b16 {%0,%1,%2,%3}, [%4];"
        : "=r"(r[0]), "=r"(r[1]), "=r"(r[2]), "=r"(r[3]) : "r"(a));
}
__device__ __forceinline__ void ldsm_x2(uint32_t* r, uint32_t a) {
    asm volatile("ldmatrix.sync.aligned.m8n8.x2.shared.b16 {%0,%1}, [%2];"
        : "=r"(r[0]), "=r"(r[1]) : "r"(a));
}
__device__ __forceinline__ void mma16816(float* d, const uint32_t* a, const uint32_t* b) {
    asm volatile("mma.sync.aligned.m16n8k16.row.col.f32.bf16.bf16.f32 "
        "{%0,%1,%2,%3}, {%4,%5,%6,%7}, {%8,%9}, {%0,%1,%2,%3};"
        : "+f"(d[0]), "+f"(d[1]), "+f"(d[2]), "+f"(d[3])
        : "r"(a[0]), "r"(a[1]), "r"(a[2]), "r"(a[3]), "r"(b[0]), "r"(b[1]));
}
__device__ __forceinline__ __nv_bfloat16 bf_hi(float x) { return __float2bfloat16_rn(x); }
__device__ __forceinline__ __nv_bfloat16 bf_lo(float x, __nv_bfloat16 hi) {
    return __float2bfloat16_rn(x - __bfloat162float(hi));
}

// ---------------------------------------------------------------------------
// bf16x3 mma.sync GEMM: C[M,N] = (Ah+Al)[M,K] @ (Bh+Bl)[N,K]^T + bias (+res)
// CTA 128x128, 8 warps (2x4), warp tile 64x32, K-chunk 32.
// 2-stage cp.async pipeline, 80KB smem -> 2 CTAs/SM. ldmatrix fragment loads.
// smem pitch 40 bf16 (80B) -> conflict-free for ldmatrix 8-row phases.
// ---------------------------------------------------------------------------
#define GK       32
#define APITCH_B 80
#define COMP_B   10240            // 128 * 80
#define STAGE_B  40960            // Ah, Al, Bh, Bl
#define GSMEM    (2 * STAGE_B)    // 81920

__device__ __forceinline__ void g_load_chunk(
    uint32_t st, int c, int tid,
    const __nv_bfloat16* __restrict__ Ah, const __nv_bfloat16* __restrict__ Al,
    const __nv_bfloat16* __restrict__ Bh, const __nv_bfloat16* __restrict__ Bl,
    int K, int m0, int n0)
{
    const int k0 = c * GK;
    #pragma unroll
    for (int i = 0; i < 2; i++) {
        int e = tid + (i << 8);          // 0..511
        int r = e >> 2, cc = e & 3;      // row, 16B chunk in 64B row
        uint32_t so = (uint32_t)(r * APITCH_B + cc * 16);
        size_t goA = (size_t)(m0 + r) * K + k0 + cc * 8;
        size_t goB = (size_t)(n0 + r) * K + k0 + cc * 8;
        cp16(st + so,             Ah + goA);
        cp16(st + COMP_B + so,    Al + goA);
        cp16(st + 2*COMP_B + so,  Bh + goB);
        cp16(st + 3*COMP_B + so,  Bl + goB);
    }
    asm volatile("cp.async.commit_group;" ::: "memory");
}

__global__ void __launch_bounds__(256, 2)
gemm_kernel(const __nv_bfloat16* __restrict__ Ah, const __nv_bfloat16* __restrict__ Al,
            const __nv_bfloat16* __restrict__ Bh, const __nv_bfloat16* __restrict__ Bl,
            const float* __restrict__ bias, const float* __restrict__ res,
            float* __restrict__ C, int K, int N)
{
    extern __shared__ __align__(16) char sm_[];
    const uint32_t sb = smem_u32(sm_);
    const int tid  = threadIdx.x;
    const int lane = tid & 31;
    const int wid  = tid >> 5;
    const int wm   = wid >> 2;          // 0..1
    const int wn   = wid & 3;           // 0..3
    const int m0 = blockIdx.y << 7;
    const int n0 = blockIdx.x << 7;
    const int NC = K / GK;

    float acc[4][4][4];
    #pragma unroll
    for (int i = 0; i < 4; i++)
        #pragma unroll
        for (int j = 0; j < 4; j++)
            #pragma unroll
            for (int q = 0; q < 4; q++) acc[i][j][q] = 0.f;

    g_load_chunk(sb,           0, tid, Ah, Al, Bh, Bl, K, m0, n0);
    g_load_chunk(sb + STAGE_B, 1, tid, Ah, Al, Bh, Bl, K, m0, n0);

    // ldmatrix per-lane source offsets (bytes)
    // A (x4): lanes 0-7 -> (rows 0-7, k0-7), 8-15 -> (rows 8-15, k0-7),
    //         16-23 -> (rows 0-7, k8-15), 24-31 -> (rows 8-15, k8-15)
    const int rowA  = (lane & 7) + ((lane >> 3) & 1) * 8;
    const int kaddA = (lane >> 4) * 16;
    const uint32_t a_ld = (uint32_t)((wm * 64 + rowA) * APITCH_B + kaddA);
    // B (x2): lanes 0-7 -> (n rows 0-7, k0-7), 8-15 -> (same rows, k8-15)
    const int rowB  = lane & 7;
    const int kaddB = ((lane >> 3) & 1) * 16;
    const uint32_t b_ld = (uint32_t)((wn * 32 + rowB) * APITCH_B + kaddB);

    for (int c = 0; c < NC; c++) {
        if (c + 1 < NC) asm volatile("cp.async.wait_group 1;" ::: "memory");
        else            asm volatile("cp.async.wait_group 0;" ::: "memory");
        __syncthreads();
        const uint32_t st = sb + (uint32_t)(c & 1) * STAGE_B;

        #pragma unroll
        for (int kh = 0; kh < 2; kh++) {
            const uint32_t abase = st + a_ld + kh * 32;
            const uint32_t bbase = st + 2*COMP_B + b_ld + kh * 32;

            uint32_t ah[4][4], bh[4][2];
            #pragma unroll
            for (int mt = 0; mt < 4; mt++)
                ldsm_x4(ah[mt], abase + mt * (16 * APITCH_B));
            #pragma unroll
            for (int nt = 0; nt < 4; nt++)
                ldsm_x2(bh[nt], bbase + nt * (8 * APITCH_B));

            // pass 1: Ah x Bh
            #pragma unroll
            for (int mt = 0; mt < 4; mt++)
                #pragma unroll
                for (int nt = 0; nt < 4; nt++)
                    mma16816(acc[mt][nt], ah[mt], bh[nt]);

            // pass 2: Ah x Bl
            uint32_t bl[4][2];
            #pragma unroll
            for (int nt = 0; nt < 4; nt++)
                ldsm_x2(bl[nt], bbase + COMP_B + nt * (8 * APITCH_B));
            #pragma unroll
            for (int mt = 0; mt < 4; mt++)
                #pragma unroll
                for (int nt = 0; nt < 4; nt++)
                    mma16816(acc[mt][nt], ah[mt], bl[nt]);

            // pass 3: Al x Bh
            uint32_t al[4][4];
            #pragma unroll
            for (int mt = 0; mt < 4; mt++)
                ldsm_x4(al[mt], abase + COMP_B + mt * (16 * APITCH_B));
            #pragma unroll
            for (int mt = 0; mt < 4; mt++)
                #pragma unroll
                for (int nt = 0; nt < 4; nt++)
                    mma16816(acc[mt][nt], al[mt], bh[nt]);
        }
        __syncthreads();
        if (c + 2 < NC)
            g_load_chunk(st, c + 2, tid, Ah, Al, Bh, Bl, K, m0, n0);
    }

    // epilogue
    #pragma unroll
    for (int mt = 0; mt < 4; mt++) {
        #pragma unroll
        for (int nt = 0; nt < 4; nt++) {
            const int rg = m0 + wm * 64 + mt * 16 + (lane >> 2);
            const int cg = n0 + wn * 32 + nt * 8 + (lane & 3) * 2;
            float2 bv = *(const float2*)(bias + cg);
            float2 o0, o1;
            o0.x = acc[mt][nt][0] + bv.x;  o0.y = acc[mt][nt][1] + bv.y;
            o1.x = acc[mt][nt][2] + bv.x;  o1.y = acc[mt][nt][3] + bv.y;
            if (res) {
                float2 r0 = *(const float2*)(res + (size_t)rg * N + cg);
                float2 r1 = *(const float2*)(res + (size_t)(rg + 8) * N + cg);
                o0.x += r0.x; o0.y += r0.y;
                o1.x += r1.x; o1.y += r1.y;
            }
            *(float2*)(C + (size_t)rg * N + cg)       = o0;
            *(float2*)(C + (size_t)(rg + 8) * N + cg) = o1;
        }
    }
}

// ---------------------------------------------------------------------------
// Weight transpose + bf16 split: W[K,N] fp32 -> Th/Tl[N,K] bf16
// ---------------------------------------------------------------------------
__global__ void __launch_bounds__(256)
transp_split(const float* __restrict__ W, __nv_bfloat16* __restrict__ Th,
             __nv_bfloat16* __restrict__ Tl, int Kd, int Nd)
{
    __shared__ float t[32][33];
    const int n0 = blockIdx.x * 32, k0 = blockIdx.y * 32;
    const int tx = threadIdx.x & 31, ty = threadIdx.x >> 5;
    #pragma unroll
    for (int i = 0; i < 4; i++) {
        int kk = ty + i * 8;
        t[kk][tx] = W[(size_t)(k0 + kk) * Nd + n0 + tx];
    }
    __syncthreads();
    #pragma unroll
    for (int i = 0; i < 4; i++) {
        int nn = ty + i * 8;
        float v = t[tx][nn];
        __nv_bfloat16 hi = bf_hi(v);
        size_t o = (size_t)(n0 + nn) * Kd + k0 + tx;
        Th[o] = hi;
        Tl[o] = bf_lo(v, hi);
    }
}

// ---------------------------------------------------------------------------
// RMSNorm -> bf16 hi/lo
// ---------------------------------------------------------------------------
__global__ void __launch_bounds__(256)
rmsnorm_split(const float* __restrict__ in, const float* __restrict__ g,
              __nv_bfloat16* __restrict__ outh, __nv_bfloat16* __restrict__ outl)
{
    __shared__ float red[8];
    const int row = blockIdx.x;
    const int tid = threadIdx.x;
    const float4* inr = (const float4*)(in + (size_t)row * DMODEL);
    float4 v0 = inr[tid];
    float4 v1 = inr[tid + 256];
    float ss = v0.x*v0.x + v0.y*v0.y + v0.z*v0.z + v0.w*v0.w
             + v1.x*v1.x + v1.y*v1.y + v1.z*v1.z + v1.w*v1.w;
    #pragma unroll
    for (int o = 16; o; o >>= 1) ss += __shfl_xor_sync(0xffffffffu, ss, o);
    if ((tid & 31) == 0) red[tid >> 5] = ss;
    __syncthreads();
    float tot = red[0]+red[1]+red[2]+red[3]+red[4]+red[5]+red[6]+red[7];
    float rs = rsqrtf(tot * (1.0f / DMODEL) + 1e-8f);

    const float4* gr = (const float4*)g;
    float4 ga = gr[tid], gb = gr[tid + 256];
    __nv_bfloat162* oh2 = (__nv_bfloat162*)(outh + (size_t)row * DMODEL);
    __nv_bfloat162* ol2 = (__nv_bfloat162*)(outl + (size_t)row * DMODEL);
    float y[8] = { v0.x*rs*ga.x, v0.y*rs*ga.y, v0.z*rs*ga.z, v0.w*rs*ga.w,
                   v1.x*rs*gb.x, v1.y*rs*gb.y, v1.z*rs*gb.z, v1.w*rs*gb.w };
    #pragma unroll
    for (int p = 0; p < 4; p++) {
        __nv_bfloat16 h0 = bf_hi(y[p*2]), h1 = bf_hi(y[p*2+1]);
        __nv_bfloat162 hh; hh.x = h0; hh.y = h1;
        __nv_bfloat162 ll; ll.x = bf_lo(y[p*2], h0); ll.y = bf_lo(y[p*2+1], h1);
        int base = (p < 2) ? (tid*2 + p) : ((tid+256)*2 + (p-2));
        oh2[base] = hh; ol2[base] = ll;
    }
}

// ---------------------------------------------------------------------------
// RoPE (in place on q,k of qkv)
// ---------------------------------------------------------------------------
__global__ void __launch_bounds__(256)
rope_kernel(float* __restrict__ qkv)
{
    const long idx = (long)blockIdx.x * 256 + threadIdx.x;
    const int  i   = (int)(idx & 63);
    const int  h   = (int)((idx >> 6) & 15);
    const long bl  = idx >> 10;
    const long l   = bl & 2047;

    float freq = expf(-(float)i * 0.14391156642875464f);
    float angle = (float)l * freq;
    float s, c;
    sincosf(angle, &s, &c);

    float* qp = qkv + bl * (3 * DMODEL) + h * HD + i;
    float* kp = qp + DMODEL;
    float q1 = qp[0], q2 = qp[64];
    float k1 = kp[0], k2 = kp[64];
    qp[0]  = q1 * c - q2 * s;
    qp[64] = q2 * c + q1 * s;
    kp[0]  = k1 * c - k2 * s;
    kp[64] = k2 * c + k1 * s;
}

// ---------------------------------------------------------------------------
// Flash attention (causal, fp32), outputs bf16 hi/lo
// ---------------------------------------------------------------------------
#define ATT_BM   64
#define ATT_BN   64
#define QSTRIDE  132
#define PSTRIDE  68
#define ATT_SMEM ((3 * ATT_BM * QSTRIDE + ATT_BM * PSTRIDE) * (int)sizeof(float))

__global__ void __launch_bounds__(256)
attn_kernel(const float* __restrict__ qkv,
            __nv_bfloat16* __restrict__ Oh, __nv_bfloat16* __restrict__ Ol)
{
    extern __shared__ float smem[];
    float* sQ = smem;
    float* sK = sQ + ATT_BM * QSTRIDE;
    float* sV = sK + ATT_BN * QSTRIDE;
    float* sP = sV + ATT_BN * QSTRIDE;

    const int bh = blockIdx.y;
    const int b  = bh >> 4;
    const int h  = bh & 15;
    const int qi = gridDim.x - 1 - blockIdx.x;
    const int q0 = qi * ATT_BM;
    const int tid = threadIdx.x;
    const int r  = tid >> 2;
    const int qd = tid & 3;

    const float* qbase = qkv + (size_t)(b * LSEQ) * (3 * DMODEL) + h * HD;
    const float* kbase = qbase + DMODEL;
    const float* vbase = qbase + 2 * DMODEL;

    for (int i = tid; i < ATT_BM * 32; i += 256) {
        int row = i >> 5, c4 = (i & 31) << 2;
        *(float4*)(sQ + row * QSTRIDE + c4) =
            *(const float4*)(qbase + (size_t)(q0 + row) * (3 * DMODEL) + c4);
    }

    float accO[32];
    #pragma unroll
    for (int i = 0; i < 32; i++) accO[i] = 0.f;
    float mrow = -1e30f, lrow = 0.f;
    const int qg = q0 + r;
    const float scale = 0.088388347648318447f;

    const int nk = qi + 1;
    for (int kt = 0; kt < nk; kt++) {
        const int k0 = kt * ATT_BN;
        __syncthreads();
        for (int i = tid; i < ATT_BN * 32; i += 256) {
            int row = i >> 5, c4 = (i & 31) << 2;
            size_t goff = (size_t)(k0 + row) * (3 * DMODEL) + c4;
            *(float4*)(sK + row * QSTRIDE + c4) = *(const float4*)(kbase + goff);
            *(float4*)(sV + row * QSTRIDE + c4) = *(const float4*)(vbase + goff);
        }
        __syncthreads();

        float s[16];
        #pragma unroll
        for (int jj = 0; jj < 16; jj++) s[jj] = 0.f;
        const float* qr = sQ + r * QSTRIDE;
        #pragma unroll 2
        for (int d = 0; d < HD; d += 4) {
            float4 qv = *(const float4*)(qr + d);
            #pragma unroll
            for (int jj = 0; jj < 16; jj++) {
                float4 kv = *(const float4*)(sK + (qd + (jj << 2)) * QSTRIDE + d);
                s[jj] = fmaf(qv.x, kv.x, s[jj]);
                s[jj] = fmaf(qv.y, kv.y, s[jj]);
                s[jj] = fmaf(qv.z, kv.z, s[jj]);
                s[jj] = fmaf(qv.w, kv.w, s[jj]);
            }
        }

        float tmax = -1e30f;
        #pragma unroll
        for (int jj = 0; jj < 16; jj++) {
            int jgl = k0 + qd + (jj << 2);
            s[jj] = (jgl <= qg) ? s[jj] * scale : -1e30f;
            tmax = fmaxf(tmax, s[jj]);
        }
        tmax = fmaxf(tmax, __shfl_xor_sync(0xffffffffu, tmax, 1));
        tmax = fmaxf(tmax, __shfl_xor_sync(0xffffffffu, tmax, 2));

        float mnew = fmaxf(mrow, tmax);
        float corr = __expf(mrow - mnew);
        float psum = 0.f;
        #pragma unroll
        for (int jj = 0; jj < 16; jj++) {
            float p = __expf(s[jj] - mnew);
            s[jj] = p;
            psum += p;
        }
        psum += __shfl_xor_sync(0xffffffffu, psum, 1);
        psum += __shfl_xor_sync(0xffffffffu, psum, 2);
        lrow = lrow * corr + psum;
        mrow = mnew;
        #pragma unroll
        for (int i = 0; i < 32; i++) accO[i] *= corr;

        #pragma unroll
        for (int jj = 0; jj < 16; jj++)
            sP[r * PSTRIDE + qd + (jj << 2)] = s[jj];
        __syncthreads();

        const float* prow = sP + r * PSTRIDE;
        #pragma unroll 4
        for (int j = 0; j < ATT_BN; j++) {
            float p = prow[j];
            const float4* vr = (const float4*)(sV + j * QSTRIDE + (qd << 5));
            #pragma unroll
            for (int cc = 0; cc < 8; cc++) {
                float4 vv = vr[cc];
                accO[cc * 4 + 0] = fmaf(p, vv.x, accO[cc * 4 + 0]);
                accO[cc * 4 + 1] = fmaf(p, vv.y, accO[cc * 4 + 1]);
                accO[cc * 4 + 2] = fmaf(p, vv.z, accO[cc * 4 + 2]);
                accO[cc * 4 + 3] = fmaf(p, vv.w, accO[cc * 4 + 3]);
            }
        }
    }

    float inv = 1.f / lrow;
    size_t base = (size_t)(b * LSEQ + qg) * DMODEL + h * HD + (qd << 5);
    __nv_bfloat162* oh2 = (__nv_bfloat162*)(Oh + base);
    __nv_bfloat162* ol2 = (__nv_bfloat162*)(Ol + base);
    #pragma unroll
    for (int cc = 0; cc < 16; cc++) {
        float w0 = accO[cc * 2] * inv;
        float w1 = accO[cc * 2 + 1] * inv;
        __nv_bfloat16 h0 = bf_hi(w0), h1 = bf_hi(w1);
        __nv_bfloat162 hh; hh.x = h0; hh.y = h1;
        __nv_bfloat162 ll; ll.x = bf_lo(w0, h0); ll.y = bf_lo(w1, h1);
        oh2[cc] = hh; ol2[cc] = ll;
    }
}

// ---------------------------------------------------------------------------
// SwiGLU -> bf16 hi/lo  (per-float4 of the OUTPUT: ROWS*4*DMODEL elements)
// ---------------------------------------------------------------------------
__global__ void __launch_bounds__(256)
swiglu_split(const float* __restrict__ P,
             __nv_bfloat16* __restrict__ Fh, __nv_bfloat16* __restrict__ Fl)
{
    size_t i4 = (size_t)blockIdx.x * 256 + threadIdx.x;  // output float4 index
    if (i4 >= (size_t)ROWS * 4 * DMODEL / 4) return;
    size_t rr  = i4 >> 11;       // 2048 float4 per 8192-wide output row
    size_t kk4 = i4 & 2047;
    const float4 gt = *(const float4*)(P + rr * 16384 + kk4 * 4);
    const float4 vl = *(const float4*)(P + rr * 16384 + 8192 + kk4 * 4);
    float f[4];
    f[0] = gt.x / (1.f + __expf(-gt.x)) * vl.x;
    f[1] = gt.y / (1.f + __expf(-gt.y)) * vl.y;
    f[2] = gt.z / (1.f + __expf(-gt.z)) * vl.z;
    f[3] = gt.w / (1.f + __expf(-gt.w)) * vl.w;
    size_t ob = rr * 8192 + kk4 * 4;
    __nv_bfloat162* fh2 = (__nv_bfloat162*)(Fh + ob);
    __nv_bfloat162* fl2 = (__nv_bfloat162*)(Fl + ob);
    #pragma unroll
    for (int p = 0; p < 2; p++) {
        __nv_bfloat16 h0 = bf_hi(f[p*2]), h1 = bf_hi(f[p*2+1]);
        __nv_bfloat162 hh; hh.x = h0; hh.y = h1;
        __nv_bfloat162 ll; ll.x = bf_lo(f[p*2], h0); ll.y = bf_lo(f[p*2+1], h1);
        fh2[p] = hh; fl2[p] = ll;
    }
}

// ---------------------------------------------------------------------------
// Host launcher
// ---------------------------------------------------------------------------
extern "C" void kernel_launch(void* const* d_in, const int* in_sizes, int n_in,
                              void* d_out, int out_size)
{
    const float* x    = (const float*)d_in[0];
    const float* Wqkv = (const float*)d_in[1];
    const float* bqkv = (const float*)d_in[2];
    const float* Wo   = (const float*)d_in[3];
    const float* bo   = (const float*)d_in[4];
    const float* g1   = (const float*)d_in[5];
    const float* g2   = (const float*)d_in[6];
    const float* Wp   = (const float*)d_in[7];
    const float* bp   = (const float*)d_in[8];
    const float* Wff  = (const float*)d_in[9];
    const float* bff  = (const float*)d_in[10];
    float* out = (float*)d_out;

    float *p_qkv, *p_x2, *p_p;
    __nv_bfloat16 *p_xnh, *p_xnl, *p_oh, *p_ol, *p_ffh, *p_ffl;
    __nv_bfloat16 *p_wqkvh, *p_wqkvl, *p_woh, *p_wol, *p_wph, *p_wpl, *p_wffh, *p_wffl;
    cudaGetSymbolAddress((void**)&p_qkv, g_qkv);
    cudaGetSymbolAddress((void**)&p_x2,  g_x2);
    cudaGetSymbolAddress((void**)&p_p,   g_p);
    cudaGetSymbolAddress((void**)&p_xnh, g_xnh);  cudaGetSymbolAddress((void**)&p_xnl, g_xnl);
    cudaGetSymbolAddress((void**)&p_oh,  g_oh);   cudaGetSymbolAddress((void**)&p_ol,  g_ol);
    cudaGetSymbolAddress((void**)&p_ffh, g_ffh);  cudaGetSymbolAddress((void**)&p_ffl, g_ffl);
    cudaGetSymbolAddress((void**)&p_wqkvh, g_wqkvh); cudaGetSymbolAddress((void**)&p_wqkvl, g_wqkvl);
    cudaGetSymbolAddress((void**)&p_woh, g_woh);  cudaGetSymbolAddress((void**)&p_wol, g_wol);
    cudaGetSymbolAddress((void**)&p_wph, g_wph);  cudaGetSymbolAddress((void**)&p_wpl, g_wpl);
    cudaGetSymbolAddress((void**)&p_wffh, g_wffh); cudaGetSymbolAddress((void**)&p_wffl, g_wffl);

    cudaFuncSetAttribute(attn_kernel, cudaFuncAttributeMaxDynamicSharedMemorySize, ATT_SMEM);
    cudaFuncSetAttribute(gemm_kernel, cudaFuncAttributeMaxDynamicSharedMemorySize, GSMEM);

    // Weight transposition + bf16 split
    transp_split<<<dim3(3 * DMODEL / 32, DMODEL / 32), 256>>>(Wqkv, p_wqkvh, p_wqkvl, DMODEL, 3 * DMODEL);
    transp_split<<<dim3(DMODEL / 32, DMODEL / 32), 256>>>(Wo, p_woh, p_wol, DMODEL, DMODEL);
    transp_split<<<dim3(8 * DMODEL / 32, DMODEL / 32), 256>>>(Wp, p_wph, p_wpl, DMODEL, 8 * DMODEL);
    transp_split<<<dim3(DMODEL / 32, 4 * DMODEL / 32), 256>>>(Wff, p_wffh, p_wffl, 4 * DMODEL, DMODEL);

    // 1. pre-norm (-> bf16 split)
    rmsnorm_split<<<ROWS, 256>>>(x, g1, p_xnh, p_xnl);

    // 2. QKV projection
    gemm_kernel<<<dim3(3 * DMODEL / 128, ROWS / 128), 256, GSMEM>>>(
        p_xnh, p_xnl, p_wqkvh, p_wqkvl, bqkv, nullptr, p_qkv, DMODEL, 3 * DMODEL);

    // 3. RoPE
    rope_kernel<<<(ROWS * NH * 64) / 256, 256>>>(p_qkv);

    // 4. causal flash attention (-> bf16 split)
    attn_kernel<<<dim3(LSEQ / ATT_BM, BD * NH), 256, ATT_SMEM>>>(p_qkv, p_oh, p_ol);

    // 5. output projection + residual
    gemm_kernel<<<dim3(DMODEL / 128, ROWS / 128), 256, GSMEM>>>(
        p_oh, p_ol, p_woh, p_wol, bo, x, p_x2, DMODEL, DMODEL);

    // 6. second pre-norm (-> bf16 split)
    rmsnorm_split<<<ROWS, 256>>>(p_x2, g2, p_xnh, p_xnl);

    // 7. FFN up-projection
    gemm_kernel<<<dim3(8 * DMODEL / 128, ROWS / 128), 256, GSMEM>>>(
        p_xnh, p_xnl, p_wph, p_wpl, bp, nullptr, p_p, DMODEL, 8 * DMODEL);

    // 8. SwiGLU (-> bf16 split)
    swiglu_split<<<(ROWS * 4 * DMODEL / 4) / 256, 256>>>(p_p, p_ffh, p_ffl);

    // 9. FFN down-projection + residual -> output
    gemm_kernel<<<dim3(DMODEL / 128, ROWS / 128), 256, GSMEM>>>(
        p_ffh, p_ffl, p_wffh, p_wffl, bff, p_x2, out, 4 * DMODEL, DMODEL);
}

// round 6
// speedup vs baseline: 1.5160x; 1.5160x over previous
#include <cuda_runtime.h>
#include <cuda_bf16.h>
#include <math.h>
#include <stdint.h>

// ---------------------------------------------------------------------------
// Problem constants
// ---------------------------------------------------------------------------
#define BD      2
#define LSEQ    2048
#define DMODEL  2048
#define NH      16
#define HD      128
#define ROWS    (BD * LSEQ)      // 4096

// ---------------------------------------------------------------------------
// Scratch (device globals -- no allocation allowed)
// ---------------------------------------------------------------------------
__device__ float g_qkv[ROWS * 3 * DMODEL];                 // 96 MB fp32
__device__ float g_x2 [ROWS * DMODEL];                     // 32 MB fp32
__device__ float g_p  [(size_t)ROWS * 8 * DMODEL];         // 256 MB fp32

__device__ __nv_bfloat16 g_xnh[ROWS * DMODEL], g_xnl[ROWS * DMODEL];
__device__ __nv_bfloat16 g_oh [ROWS * DMODEL], g_ol [ROWS * DMODEL];
__device__ __nv_bfloat16 g_ffh[(size_t)ROWS * 4 * DMODEL], g_ffl[(size_t)ROWS * 4 * DMODEL];
// transposed weights [N, K] bf16 hi/lo
__device__ __nv_bfloat16 g_wqkvh[3 * DMODEL * DMODEL], g_wqkvl[3 * DMODEL * DMODEL];
__device__ __nv_bfloat16 g_woh  [DMODEL * DMODEL],     g_wol  [DMODEL * DMODEL];
__device__ __nv_bfloat16 g_wph  [(size_t)8 * DMODEL * DMODEL], g_wpl[(size_t)8 * DMODEL * DMODEL];
__device__ __nv_bfloat16 g_wffh [(size_t)4 * DMODEL * DMODEL], g_wffl[(size_t)4 * DMODEL * DMODEL];

// ---------------------------------------------------------------------------
// Helpers
// ---------------------------------------------------------------------------
__device__ __forceinline__ uint32_t smem_u32(const void* p) {
    uint32_t a;
    asm("{ .reg .u64 t; cvta.to.shared.u64 t, %1; cvt.u32.u64 %0, t; }"
        : "=r"(a) : "l"(p));
    return a;
}
__device__ __forceinline__ void cp16(uint32_t dst, const void* src) {
    asm volatile("cp.async.cg.shared.global [%0], [%1], 16;" :: "r"(dst), "l"(src));
}
__device__ __forceinline__ void ldsm_x4(uint32_t* r, uint32_t a) {
    asm volatile("ldmatrix.sync.aligned.m8n8.x4.shared.b16 {%0,%1,%2,%3}, [%4];"
        : "=r"(r[0]), "=r"(r[1]), "=r"(r[2]), "=r"(r[3]) : "r"(a));
}
__device__ __forceinline__ void ldsm_x2(uint32_t* r, uint32_t a) {
    asm volatile("ldmatrix.sync.aligned.m8n8.x2.shared.b16 {%0,%1}, [%2];"
        : "=r"(r[0]), "=r"(r[1]) : "r"(a));
}
__device__ __forceinline__ void mma16816(float* d, const uint32_t* a, const uint32_t* b) {
    asm volatile("mma.sync.aligned.m16n8k16.row.col.f32.bf16.bf16.f32 "
        "{%0,%1,%2,%3}, {%4,%5,%6,%7}, {%8,%9}, {%0,%1,%2,%3};"
        : "+f"(d[0]), "+f"(d[1]), "+f"(d[2]), "+f"(d[3])
        : "r"(a[0]), "r"(a[1]), "r"(a[2]), "r"(a[3]), "r"(b[0]), "r"(b[1]));
}
__device__ __forceinline__ __nv_bfloat16 bf_hi(float x) { return __float2bfloat16_rn(x); }
__device__ __forceinline__ __nv_bfloat16 bf_lo(float x, __nv_bfloat16 hi) {
    return __float2bfloat16_rn(x - __bfloat162float(hi));
}

// ---------------------------------------------------------------------------
// bf16x3 mma.sync GEMM: C[M,N] = (Ah+Al)[M,K] @ (Bh+Bl)[N,K]^T + bias (+res)
// CTA 128x128, 8 warps (2x4), warp tile 64x32, K-chunk 32.
// 4-stage cp.async pipeline (164KB smem), ONE syncthreads per chunk,
// prefetch issued BEFORE compute (targets the slot consumed last iteration).
// smem pitch 40 bf16 (80B) -> conflict-free for ldmatrix 8-row phases.
// ---------------------------------------------------------------------------
#define GK       32
#define APITCH_B 80
#define COMP_B   10240            // 128 * 80
#define STAGE_B  40960            // Ah, Al, Bh, Bl
#define NSTAGE   4
#define GSMEM    (NSTAGE * STAGE_B)   // 163840

__device__ __forceinline__ void g_load_chunk(
    uint32_t st, int c, int tid,
    const __nv_bfloat16* __restrict__ Ah, const __nv_bfloat16* __restrict__ Al,
    const __nv_bfloat16* __restrict__ Bh, const __nv_bfloat16* __restrict__ Bl,
    int K, int m0, int n0)
{
    const int k0 = c * GK;
    #pragma unroll
    for (int i = 0; i < 2; i++) {
        int e = tid + (i << 8);          // 0..511
        int r = e >> 2, cc = e & 3;      // row, 16B chunk in 64B row
        uint32_t so = (uint32_t)(r * APITCH_B + cc * 16);
        size_t goA = (size_t)(m0 + r) * K + k0 + cc * 8;
        size_t goB = (size_t)(n0 + r) * K + k0 + cc * 8;
        cp16(st + so,             Ah + goA);
        cp16(st + COMP_B + so,    Al + goA);
        cp16(st + 2*COMP_B + so,  Bh + goB);
        cp16(st + 3*COMP_B + so,  Bl + goB);
    }
    asm volatile("cp.async.commit_group;" ::: "memory");
}

__global__ void __launch_bounds__(256)
gemm_kernel(const __nv_bfloat16* __restrict__ Ah, const __nv_bfloat16* __restrict__ Al,
            const __nv_bfloat16* __restrict__ Bh, const __nv_bfloat16* __restrict__ Bl,
            const float* __restrict__ bias, const float* __restrict__ res,
            float* __restrict__ C, int K, int N)
{
    extern __shared__ __align__(16) char sm_[];
    const uint32_t sb = smem_u32(sm_);
    const int tid  = threadIdx.x;
    const int lane = tid & 31;
    const int wid  = tid >> 5;
    const int wm   = wid >> 2;          // 0..1
    const int wn   = wid & 3;           // 0..3
    const int m0 = blockIdx.y << 7;
    const int n0 = blockIdx.x << 7;
    const int NC = K / GK;

    float acc[4][4][4];
    #pragma unroll
    for (int i = 0; i < 4; i++)
        #pragma unroll
        for (int j = 0; j < 4; j++)
            #pragma unroll
            for (int q = 0; q < 4; q++) acc[i][j][q] = 0.f;

    // prologue: fill 3 of 4 stages
    g_load_chunk(sb,               0, tid, Ah, Al, Bh, Bl, K, m0, n0);
    g_load_chunk(sb + STAGE_B,     1, tid, Ah, Al, Bh, Bl, K, m0, n0);
    g_load_chunk(sb + 2 * STAGE_B, 2, tid, Ah, Al, Bh, Bl, K, m0, n0);

    // ldmatrix per-lane source offsets (bytes)
    const int rowA  = (lane & 7) + ((lane >> 3) & 1) * 8;
    const int kaddA = (lane >> 4) * 16;
    const uint32_t a_ld = (uint32_t)((wm * 64 + rowA) * APITCH_B + kaddA);
    const int rowB  = lane & 7;
    const int kaddB = ((lane >> 3) & 1) * 16;
    const uint32_t b_ld = (uint32_t)((wn * 32 + rowB) * APITCH_B + kaddB);

    for (int c = 0; c < NC; c++) {
        // wait until chunk c has landed (at most the 2 younger groups pending)
        asm volatile("cp.async.wait_group 2;" ::: "memory");
        __syncthreads();   // all warps done reading slot (c-1)%4; chunk c visible

        // prefetch chunk c+3 into slot (c+3)%4 == (c-1)%4 (consumed last iter)
        if (c + 3 < NC)
            g_load_chunk(sb + (uint32_t)((c + 3) & 3) * STAGE_B, c + 3, tid,
                         Ah, Al, Bh, Bl, K, m0, n0);

        const uint32_t st = sb + (uint32_t)(c & 3) * STAGE_B;

        #pragma unroll
        for (int kh = 0; kh < 2; kh++) {
            const uint32_t abase = st + a_ld + kh * 32;
            const uint32_t bbase = st + 2*COMP_B + b_ld + kh * 32;

            uint32_t ah[4][4], bh[4][2];
            #pragma unroll
            for (int mt = 0; mt < 4; mt++)
                ldsm_x4(ah[mt], abase + mt * (16 * APITCH_B));
            #pragma unroll
            for (int nt = 0; nt < 4; nt++)
                ldsm_x2(bh[nt], bbase + nt * (8 * APITCH_B));

            // pass 1: Ah x Bh
            #pragma unroll
            for (int mt = 0; mt < 4; mt++)
                #pragma unroll
                for (int nt = 0; nt < 4; nt++)
                    mma16816(acc[mt][nt], ah[mt], bh[nt]);

            // pass 2: Ah x Bl
            uint32_t bl[4][2];
            #pragma unroll
            for (int nt = 0; nt < 4; nt++)
                ldsm_x2(bl[nt], bbase + COMP_B + nt * (8 * APITCH_B));
            #pragma unroll
            for (int mt = 0; mt < 4; mt++)
                #pragma unroll
                for (int nt = 0; nt < 4; nt++)
                    mma16816(acc[mt][nt], ah[mt], bl[nt]);

            // pass 3: Al x Bh
            uint32_t al[4][4];
            #pragma unroll
            for (int mt = 0; mt < 4; mt++)
                ldsm_x4(al[mt], abase + COMP_B + mt * (16 * APITCH_B));
            #pragma unroll
            for (int mt = 0; mt < 4; mt++)
                #pragma unroll
                for (int nt = 0; nt < 4; nt++)
                    mma16816(acc[mt][nt], al[mt], bh[nt]);
        }
    }

    // epilogue (registers only; no smem reuse -> no sync needed)
    #pragma unroll
    for (int mt = 0; mt < 4; mt++) {
        #pragma unroll
        for (int nt = 0; nt < 4; nt++) {
            const int rg = m0 + wm * 64 + mt * 16 + (lane >> 2);
            const int cg = n0 + wn * 32 + nt * 8 + (lane & 3) * 2;
            float2 bv = *(const float2*)(bias + cg);
            float2 o0, o1;
            o0.x = acc[mt][nt][0] + bv.x;  o0.y = acc[mt][nt][1] + bv.y;
            o1.x = acc[mt][nt][2] + bv.x;  o1.y = acc[mt][nt][3] + bv.y;
            if (res) {
                float2 r0 = *(const float2*)(res + (size_t)rg * N + cg);
                float2 r1 = *(const float2*)(res + (size_t)(rg + 8) * N + cg);
                o0.x += r0.x; o0.y += r0.y;
                o1.x += r1.x; o1.y += r1.y;
            }
            *(float2*)(C + (size_t)rg * N + cg)       = o0;
            *(float2*)(C + (size_t)(rg + 8) * N + cg) = o1;
        }
    }
}

// ---------------------------------------------------------------------------
// Weight transpose + bf16 split: W[K,N] fp32 -> Th/Tl[N,K] bf16
// ---------------------------------------------------------------------------
__global__ void __launch_bounds__(256)
transp_split(const float* __restrict__ W, __nv_bfloat16* __restrict__ Th,
             __nv_bfloat16* __restrict__ Tl, int Kd, int Nd)
{
    __shared__ float t[32][33];
    const int n0 = blockIdx.x * 32, k0 = blockIdx.y * 32;
    const int tx = threadIdx.x & 31, ty = threadIdx.x >> 5;
    #pragma unroll
    for (int i = 0; i < 4; i++) {
        int kk = ty + i * 8;
        t[kk][tx] = W[(size_t)(k0 + kk) * Nd + n0 + tx];
    }
    __syncthreads();
    #pragma unroll
    for (int i = 0; i < 4; i++) {
        int nn = ty + i * 8;
        float v = t[tx][nn];
        __nv_bfloat16 hi = bf_hi(v);
        size_t o = (size_t)(n0 + nn) * Kd + k0 + tx;
        Th[o] = hi;
        Tl[o] = bf_lo(v, hi);
    }
}

// ---------------------------------------------------------------------------
// RMSNorm -> bf16 hi/lo
// ---------------------------------------------------------------------------
__global__ void __launch_bounds__(256)
rmsnorm_split(const float* __restrict__ in, const float* __restrict__ g,
              __nv_bfloat16* __restrict__ outh, __nv_bfloat16* __restrict__ outl)
{
    __shared__ float red[8];
    const int row = blockIdx.x;
    const int tid = threadIdx.x;
    const float4* inr = (const float4*)(in + (size_t)row * DMODEL);
    float4 v0 = inr[tid];
    float4 v1 = inr[tid + 256];
    float ss = v0.x*v0.x + v0.y*v0.y + v0.z*v0.z + v0.w*v0.w
             + v1.x*v1.x + v1.y*v1.y + v1.z*v1.z + v1.w*v1.w;
    #pragma unroll
    for (int o = 16; o; o >>= 1) ss += __shfl_xor_sync(0xffffffffu, ss, o);
    if ((tid & 31) == 0) red[tid >> 5] = ss;
    __syncthreads();
    float tot = red[0]+red[1]+red[2]+red[3]+red[4]+red[5]+red[6]+red[7];
    float rs = rsqrtf(tot * (1.0f / DMODEL) + 1e-8f);

    const float4* gr = (const float4*)g;
    float4 ga = gr[tid], gb = gr[tid + 256];
    __nv_bfloat162* oh2 = (__nv_bfloat162*)(outh + (size_t)row * DMODEL);
    __nv_bfloat162* ol2 = (__nv_bfloat162*)(outl + (size_t)row * DMODEL);
    float y[8] = { v0.x*rs*ga.x, v0.y*rs*ga.y, v0.z*rs*ga.z, v0.w*rs*ga.w,
                   v1.x*rs*gb.x, v1.y*rs*gb.y, v1.z*rs*gb.z, v1.w*rs*gb.w };
    #pragma unroll
    for (int p = 0; p < 4; p++) {
        __nv_bfloat16 h0 = bf_hi(y[p*2]), h1 = bf_hi(y[p*2+1]);
        __nv_bfloat162 hh; hh.x = h0; hh.y = h1;
        __nv_bfloat162 ll; ll.x = bf_lo(y[p*2], h0); ll.y = bf_lo(y[p*2+1], h1);
        int base = (p < 2) ? (tid*2 + p) : ((tid+256)*2 + (p-2));
        oh2[base] = hh; ol2[base] = ll;
    }
}

// ---------------------------------------------------------------------------
// RoPE (in place on q,k of qkv)
// ---------------------------------------------------------------------------
__global__ void __launch_bounds__(256)
rope_kernel(float* __restrict__ qkv)
{
    const long idx = (long)blockIdx.x * 256 + threadIdx.x;
    const int  i   = (int)(idx & 63);
    const int  h   = (int)((idx >> 6) & 15);
    const long bl  = idx >> 10;
    const long l   = bl & 2047;

    float freq = expf(-(float)i * 0.14391156642875464f);
    float angle = (float)l * freq;
    float s, c;
    sincosf(angle, &s, &c);

    float* qp = qkv + bl * (3 * DMODEL) + h * HD + i;
    float* kp = qp + DMODEL;
    float q1 = qp[0], q2 = qp[64];
    float k1 = kp[0], k2 = kp[64];
    qp[0]  = q1 * c - q2 * s;
    qp[64] = q2 * c + q1 * s;
    kp[0]  = k1 * c - k2 * s;
    kp[64] = k2 * c + k1 * s;
}

// ---------------------------------------------------------------------------
// Flash attention (causal, fp32), outputs bf16 hi/lo
// ---------------------------------------------------------------------------
#define ATT_BM   64
#define ATT_BN   64
#define QSTRIDE  132
#define PSTRIDE  68
#define ATT_SMEM ((3 * ATT_BM * QSTRIDE + ATT_BM * PSTRIDE) * (int)sizeof(float))

__global__ void __launch_bounds__(256)
attn_kernel(const float* __restrict__ qkv,
            __nv_bfloat16* __restrict__ Oh, __nv_bfloat16* __restrict__ Ol)
{
    extern __shared__ float smem[];
    float* sQ = smem;
    float* sK = sQ + ATT_BM * QSTRIDE;
    float* sV = sK + ATT_BN * QSTRIDE;
    float* sP = sV + ATT_BN * QSTRIDE;

    const int bh = blockIdx.y;
    const int b  = bh >> 4;
    const int h  = bh & 15;
    const int qi = gridDim.x - 1 - blockIdx.x;
    const int q0 = qi * ATT_BM;
    const int tid = threadIdx.x;
    const int r  = tid >> 2;
    const int qd = tid & 3;

    const float* qbase = qkv + (size_t)(b * LSEQ) * (3 * DMODEL) + h * HD;
    const float* kbase = qbase + DMODEL;
    const float* vbase = qbase + 2 * DMODEL;

    for (int i = tid; i < ATT_BM * 32; i += 256) {
        int row = i >> 5, c4 = (i & 31) << 2;
        *(float4*)(sQ + row * QSTRIDE + c4) =
            *(const float4*)(qbase + (size_t)(q0 + row) * (3 * DMODEL) + c4);
    }

    float accO[32];
    #pragma unroll
    for (int i = 0; i < 32; i++) accO[i] = 0.f;
    float mrow = -1e30f, lrow = 0.f;
    const int qg = q0 + r;
    const float scale = 0.088388347648318447f;

    const int nk = qi + 1;
    for (int kt = 0; kt < nk; kt++) {
        const int k0 = kt * ATT_BN;
        __syncthreads();
        for (int i = tid; i < ATT_BN * 32; i += 256) {
            int row = i >> 5, c4 = (i & 31) << 2;
            size_t goff = (size_t)(k0 + row) * (3 * DMODEL) + c4;
            *(float4*)(sK + row * QSTRIDE + c4) = *(const float4*)(kbase + goff);
            *(float4*)(sV + row * QSTRIDE + c4) = *(const float4*)(vbase + goff);
        }
        __syncthreads();

        float s[16];
        #pragma unroll
        for (int jj = 0; jj < 16; jj++) s[jj] = 0.f;
        const float* qr = sQ + r * QSTRIDE;
        #pragma unroll 2
        for (int d = 0; d < HD; d += 4) {
            float4 qv = *(const float4*)(qr + d);
            #pragma unroll
            for (int jj = 0; jj < 16; jj++) {
                float4 kv = *(const float4*)(sK + (qd + (jj << 2)) * QSTRIDE + d);
                s[jj] = fmaf(qv.x, kv.x, s[jj]);
                s[jj] = fmaf(qv.y, kv.y, s[jj]);
                s[jj] = fmaf(qv.z, kv.z, s[jj]);
                s[jj] = fmaf(qv.w, kv.w, s[jj]);
            }
        }

        float tmax = -1e30f;
        #pragma unroll
        for (int jj = 0; jj < 16; jj++) {
            int jgl = k0 + qd + (jj << 2);
            s[jj] = (jgl <= qg) ? s[jj] * scale : -1e30f;
            tmax = fmaxf(tmax, s[jj]);
        }
        tmax = fmaxf(tmax, __shfl_xor_sync(0xffffffffu, tmax, 1));
        tmax = fmaxf(tmax, __shfl_xor_sync(0xffffffffu, tmax, 2));

        float mnew = fmaxf(mrow, tmax);
        float corr = __expf(mrow - mnew);
        float psum = 0.f;
        #pragma unroll
        for (int jj = 0; jj < 16; jj++) {
            float p = __expf(s[jj] - mnew);
            s[jj] = p;
            psum += p;
        }
        psum += __shfl_xor_sync(0xffffffffu, psum, 1);
        psum += __shfl_xor_sync(0xffffffffu, psum, 2);
        lrow = lrow * corr + psum;
        mrow = mnew;
        #pragma unroll
        for (int i = 0; i < 32; i++) accO[i] *= corr;

        #pragma unroll
        for (int jj = 0; jj < 16; jj++)
            sP[r * PSTRIDE + qd + (jj << 2)] = s[jj];
        __syncthreads();

        const float* prow = sP + r * PSTRIDE;
        #pragma unroll 4
        for (int j = 0; j < ATT_BN; j++) {
            float p = prow[j];
            const float4* vr = (const float4*)(sV + j * QSTRIDE + (qd << 5));
            #pragma unroll
            for (int cc = 0; cc < 8; cc++) {
                float4 vv = vr[cc];
                accO[cc * 4 + 0] = fmaf(p, vv.x, accO[cc * 4 + 0]);
                accO[cc * 4 + 1] = fmaf(p, vv.y, accO[cc * 4 + 1]);
                accO[cc * 4 + 2] = fmaf(p, vv.z, accO[cc * 4 + 2]);
                accO[cc * 4 + 3] = fmaf(p, vv.w, accO[cc * 4 + 3]);
            }
        }
    }

    float inv = 1.f / lrow;
    size_t base = (size_t)(b * LSEQ + qg) * DMODEL + h * HD + (qd << 5);
    __nv_bfloat162* oh2 = (__nv_bfloat162*)(Oh + base);
    __nv_bfloat162* ol2 = (__nv_bfloat162*)(Ol + base);
    #pragma unroll
    for (int cc = 0; cc < 16; cc++) {
        float w0 = accO[cc * 2] * inv;
        float w1 = accO[cc * 2 + 1] * inv;
        __nv_bfloat16 h0 = bf_hi(w0), h1 = bf_hi(w1);
        __nv_bfloat162 hh; hh.x = h0; hh.y = h1;
        __nv_bfloat162 ll; ll.x = bf_lo(w0, h0); ll.y = bf_lo(w1, h1);
        oh2[cc] = hh; ol2[cc] = ll;
    }
}

// ---------------------------------------------------------------------------
// SwiGLU -> bf16 hi/lo  (per-float4 of the OUTPUT: ROWS*4*DMODEL elements)
// ---------------------------------------------------------------------------
__global__ void __launch_bounds__(256)
swiglu_split(const float* __restrict__ P,
             __nv_bfloat16* __restrict__ Fh, __nv_bfloat16* __restrict__ Fl)
{
    size_t i4 = (size_t)blockIdx.x * 256 + threadIdx.x;  // output float4 index
    if (i4 >= (size_t)ROWS * 4 * DMODEL / 4) return;
    size_t rr  = i4 >> 11;       // 2048 float4 per 8192-wide output row
    size_t kk4 = i4 & 2047;
    const float4 gt = *(const float4*)(P + rr * 16384 + kk4 * 4);
    const float4 vl = *(const float4*)(P + rr * 16384 + 8192 + kk4 * 4);
    float f[4];
    f[0] = gt.x / (1.f + __expf(-gt.x)) * vl.x;
    f[1] = gt.y / (1.f + __expf(-gt.y)) * vl.y;
    f[2] = gt.z / (1.f + __expf(-gt.z)) * vl.z;
    f[3] = gt.w / (1.f + __expf(-gt.w)) * vl.w;
    size_t ob = rr * 8192 + kk4 * 4;
    __nv_bfloat162* fh2 = (__nv_bfloat162*)(Fh + ob);
    __nv_bfloat162* fl2 = (__nv_bfloat162*)(Fl + ob);
    #pragma unroll
    for (int p = 0; p < 2; p++) {
        __nv_bfloat16 h0 = bf_hi(f[p*2]), h1 = bf_hi(f[p*2+1]);
        __nv_bfloat162 hh; hh.x = h0; hh.y = h1;
        __nv_bfloat162 ll; ll.x = bf_lo(f[p*2], h0); ll.y = bf_lo(f[p*2+1], h1);
        fh2[p] = hh; fl2[p] = ll;
    }
}

// ---------------------------------------------------------------------------
// Host launcher
// ---------------------------------------------------------------------------
extern "C" void kernel_launch(void* const* d_in, const int* in_sizes, int n_in,
                              void* d_out, int out_size)
{
    const float* x    = (const float*)d_in[0];
    const float* Wqkv = (const float*)d_in[1];
    const float* bqkv = (const float*)d_in[2];
    const float* Wo   = (const float*)d_in[3];
    const float* bo   = (const float*)d_in[4];
    const float* g1   = (const float*)d_in[5];
    const float* g2   = (const float*)d_in[6];
    const float* Wp   = (const float*)d_in[7];
    const float* bp   = (const float*)d_in[8];
    const float* Wff  = (const float*)d_in[9];
    const float* bff  = (const float*)d_in[10];
    float* out = (float*)d_out;

    float *p_qkv, *p_x2, *p_p;
    __nv_bfloat16 *p_xnh, *p_xnl, *p_oh, *p_ol, *p_ffh, *p_ffl;
    __nv_bfloat16 *p_wqkvh, *p_wqkvl, *p_woh, *p_wol, *p_wph, *p_wpl, *p_wffh, *p_wffl;
    cudaGetSymbolAddress((void**)&p_qkv, g_qkv);
    cudaGetSymbolAddress((void**)&p_x2,  g_x2);
    cudaGetSymbolAddress((void**)&p_p,   g_p);
    cudaGetSymbolAddress((void**)&p_xnh, g_xnh);  cudaGetSymbolAddress((void**)&p_xnl, g_xnl);
    cudaGetSymbolAddress((void**)&p_oh,  g_oh);   cudaGetSymbolAddress((void**)&p_ol,  g_ol);
    cudaGetSymbolAddress((void**)&p_ffh, g_ffh);  cudaGetSymbolAddress((void**)&p_ffl, g_ffl);
    cudaGetSymbolAddress((void**)&p_wqkvh, g_wqkvh); cudaGetSymbolAddress((void**)&p_wqkvl, g_wqkvl);
    cudaGetSymbolAddress((void**)&p_woh, g_woh);  cudaGetSymbolAddress((void**)&p_wol, g_wol);
    cudaGetSymbolAddress((void**)&p_wph, g_wph);  cudaGetSymbolAddress((void**)&p_wpl, g_wpl);
    cudaGetSymbolAddress((void**)&p_wffh, g_wffh); cudaGetSymbolAddress((void**)&p_wffl, g_wffl);

    cudaFuncSetAttribute(attn_kernel, cudaFuncAttributeMaxDynamicSharedMemorySize, ATT_SMEM);
    cudaFuncSetAttribute(gemm_kernel, cudaFuncAttributeMaxDynamicSharedMemorySize, GSMEM);

    // Weight transposition + bf16 split
    transp_split<<<dim3(3 * DMODEL / 32, DMODEL / 32), 256>>>(Wqkv, p_wqkvh, p_wqkvl, DMODEL, 3 * DMODEL);
    transp_split<<<dim3(DMODEL / 32, DMODEL / 32), 256>>>(Wo, p_woh, p_wol, DMODEL, DMODEL);
    transp_split<<<dim3(8 * DMODEL / 32, DMODEL / 32), 256>>>(Wp, p_wph, p_wpl, DMODEL, 8 * DMODEL);
    transp_split<<<dim3(DMODEL / 32, 4 * DMODEL / 32), 256>>>(Wff, p_wffh, p_wffl, 4 * DMODEL, DMODEL);

    // 1. pre-norm (-> bf16 split)
    rmsnorm_split<<<ROWS, 256>>>(x, g1, p_xnh, p_xnl);

    // 2. QKV projection
    gemm_kernel<<<dim3(3 * DMODEL / 128, ROWS / 128), 256, GSMEM>>>(
        p_xnh, p_xnl, p_wqkvh, p_wqkvl, bqkv, nullptr, p_qkv, DMODEL, 3 * DMODEL);

    // 3. RoPE
    rope_kernel<<<(ROWS * NH * 64) / 256, 256>>>(p_qkv);

    // 4. causal flash attention (-> bf16 split)
    attn_kernel<<<dim3(LSEQ / ATT_BM, BD * NH), 256, ATT_SMEM>>>(p_qkv, p_oh, p_ol);

    // 5. output projection + residual
    gemm_kernel<<<dim3(DMODEL / 128, ROWS / 128), 256, GSMEM>>>(
        p_oh, p_ol, p_woh, p_wol, bo, x, p_x2, DMODEL, DMODEL);

    // 6. second pre-norm (-> bf16 split)
    rmsnorm_split<<<ROWS, 256>>>(p_x2, g2, p_xnh, p_xnl);

    // 7. FFN up-projection
    gemm_kernel<<<dim3(8 * DMODEL / 128, ROWS / 128), 256, GSMEM>>>(
        p_xnh, p_xnl, p_wph, p_wpl, bp, nullptr, p_p, DMODEL, 8 * DMODEL);

    // 8. SwiGLU (-> bf16 split)
    swiglu_split<<<(ROWS * 4 * DMODEL / 4) / 256, 256>>>(p_p, p_ffh, p_ffl);

    // 9. FFN down-projection + residual -> output
    gemm_kernel<<<dim3(DMODEL / 128, ROWS / 128), 256, GSMEM>>>(
        p_ffh, p_ffl, p_wffh, p_wffl, bff, p_x2, out, 4 * DMODEL, DMODEL);
}